// round 12
// baseline (speedup 1.0000x reference)
#include <cuda_runtime.h>
#include <cuda_fp16.h>
#include <cstdint>

#define BATCH  4
#define SEQ    2048
#define HEADS  8
#define DEPTH  64
#define DMODEL 512
#define MROWS  (BATCH*SEQ)   // 8192
#define WSZ    ((size_t)DMODEL * DMODEL)

// fp16 scratch (allocation-free rule: __device__ globals)
__device__ __half g_xh[MROWS * DMODEL];
__device__ __half g_Wh[4 * DMODEL * DMODEL];   // Wq, Wk, Wv, Wo
__device__ __half g_Qh[MROWS * DMODEL];
__device__ __half g_Kh[MROWS * DMODEL];
__device__ __half g_Vh[MROWS * DMODEL];
__device__ __half g_Ah[MROWS * DMODEL];

// ---------------- helpers ----------------
__device__ __forceinline__ uint32_t h2(float lo, float hi) {
    uint32_t r;
    asm("cvt.rn.f16x2.f32 %0, %1, %2;" : "=r"(r) : "f"(hi), "f"(lo));
    return r;
}
__device__ __forceinline__ void mma16(float* d, const uint32_t* a, const uint32_t* b) {
    asm volatile(
        "mma.sync.aligned.m16n8k16.row.col.f32.f16.f16.f32 "
        "{%0,%1,%2,%3}, {%4,%5,%6,%7}, {%8,%9}, {%0,%1,%2,%3};"
        : "+f"(d[0]), "+f"(d[1]), "+f"(d[2]), "+f"(d[3])
        : "r"(a[0]), "r"(a[1]), "r"(a[2]), "r"(a[3]), "r"(b[0]), "r"(b[1]));
}
__device__ __forceinline__ float ex2f(float x) {
    float r; asm("ex2.approx.f32 %0, %1;" : "=f"(r) : "f"(x));
    return r;
}
__device__ __forceinline__ uint32_t smem_u32(const void* p) {
    uint32_t a;
    asm("{ .reg .u64 t; cvta.to.shared.u64 t, %1; cvt.u32.u64 %0, t; }" : "=r"(a) : "l"(p));
    return a;
}
__device__ __forceinline__ void ldmx4(uint32_t* r, uint32_t addr) {   // non-trans
    asm volatile(
        "ldmatrix.sync.aligned.m8n8.x4.shared.b16 {%0,%1,%2,%3}, [%4];"
        : "=r"(r[0]), "=r"(r[1]), "=r"(r[2]), "=r"(r[3]) : "r"(addr));
}
__device__ __forceinline__ void ldmx4t(uint32_t* r, uint32_t addr) {  // transposed
    asm volatile(
        "ldmatrix.sync.aligned.m8n8.x4.trans.shared.b16 {%0,%1,%2,%3}, [%4];"
        : "=r"(r[0]), "=r"(r[1]), "=r"(r[2]), "=r"(r[3]) : "r"(addr));
}
__device__ __forceinline__ void cp16(uint32_t dst, const void* src) {
    asm volatile("cp.async.cg.shared.global [%0], [%1], 16;" :: "r"(dst), "l"(src));
}
#define CP_COMMIT() asm volatile("cp.async.commit_group;" ::: "memory")
#define CP_WAIT1()  asm volatile("cp.async.wait_group 1;" ::: "memory")
#define CP_WAIT2()  asm volatile("cp.async.wait_group 2;" ::: "memory")

// ---------------------------------------------------------------------------
// fused fp32 -> fp16 conversion: x + 4 weights in ONE launch
// ---------------------------------------------------------------------------
__global__ void cvt_all(
    const float4* __restrict__ x,
    const float4* __restrict__ w0, const float4* __restrict__ w1,
    const float4* __restrict__ w2, const float4* __restrict__ w3,
    uint2* __restrict__ xh, uint2* __restrict__ wh)
{
    const int n4x = MROWS * DMODEL / 4;
    const int n4w = DMODEL * DMODEL / 4;
    int i = blockIdx.x * blockDim.x + threadIdx.x;
    if (i < n4x) {
        float4 v = x[i];
        xh[i] = make_uint2(h2(v.x, v.y), h2(v.z, v.w));
    } else {
        int j = i - n4x;
        if (j < 4 * n4w) {
            int sel = j / n4w, r = j - sel * n4w;
            const float4* s = sel == 0 ? w0 : (sel == 1 ? w1 : (sel == 2 ? w2 : w3));
            float4 v = s[r];
            wh[j] = make_uint2(h2(v.x, v.y), h2(v.z, v.w));
        }
    }
}

// ---------------------------------------------------------------------------
// GEMM: out[m][n] = sum_k A[m][k] * W[n][k]   (fp16 in, fp32 accum)
// CTA 128x128, 8 warps (2M x 4N), warp 64x32, BK=32. cp.async 4-stage.
// dyn smem = 4*2*10240 = 81920 B. Fused N-select: bx>>2 picks W/out.
// ---------------------------------------------------------------------------
template<int OUT_HALF>
__global__ __launch_bounds__(256, 2) void gemm_h(
    const __half* __restrict__ A, const __half* __restrict__ W,
    void* __restrict__ O0, void* __restrict__ O1, void* __restrict__ O2)
{
    extern __shared__ uint32_t sm[];
    const uint32_t asa = smem_u32(sm), wsa = asa + 40960;

    const int tid = threadIdx.x, wid = tid >> 5, lane = tid & 31;
    const int g = lane >> 2, t = lane & 3;
    const int wm = wid & 1, wn = wid >> 1;
    const int bx = blockIdx.x;
    const int sel = bx >> 2, n0 = (bx & 3) << 7;
    const int m0 = blockIdx.y * 128;
    void* outp = sel == 0 ? O0 : (sel == 1 ? O1 : O2);

    const __half* Ab = A + (size_t)m0 * DMODEL;
    const __half* Wb = W + (size_t)sel * WSZ + (size_t)n0 * DMODEL;

    const int l7 = lane & 7;
    const int a_row = ((lane >> 3) & 1) * 8 + l7, a_ch = ((lane >> 4) & 1) * 8;
    const int w_row = ((lane >> 4) & 1) * 8 + l7, w_ch = ((lane >> 3) & 1) * 8;

    // prologue: chunks 0..2
    #pragma unroll
    for (int s = 0; s < 3; s++) {
        #pragma unroll
        for (int j = 0; j < 2; j++) {
            int idx = tid + 256 * j, r = idx >> 2, c = idx & 3;
            cp16(asa + (s * 2560 + r * 20 + c * 4) * 4, Ab + (size_t)r * DMODEL + s * 32 + c * 8);
            cp16(wsa + (s * 2560 + r * 20 + c * 4) * 4, Wb + (size_t)r * DMODEL + s * 32 + c * 8);
        }
        CP_COMMIT();
    }

    float acc[4][4][4] = {};

    for (int kc = 0; kc < 16; kc++) {
        const int buf = kc & 3;
        CP_WAIT2();
        __syncthreads();
        if (kc + 3 < 16) {
            int b2 = (kc + 3) & 3, k0 = (kc + 3) * 32;
            #pragma unroll
            for (int j = 0; j < 2; j++) {
                int idx = tid + 256 * j, r = idx >> 2, c = idx & 3;
                cp16(asa + (b2 * 2560 + r * 20 + c * 4) * 4, Ab + (size_t)r * DMODEL + k0 + c * 8);
                cp16(wsa + (b2 * 2560 + r * 20 + c * 4) * 4, Wb + (size_t)r * DMODEL + k0 + c * 8);
            }
        }
        CP_COMMIT();

        const uint32_t ab = asa + buf * 10240;   // bytes
        const uint32_t wb = wsa + buf * 10240;
        #pragma unroll
        for (int kk = 0; kk < 2; kk++) {
            uint32_t af[4][4], wf[2][4];
            #pragma unroll
            for (int mi = 0; mi < 4; mi++)
                ldmx4(af[mi], ab + ((wm * 64 + mi * 16 + a_row) * 40 + kk * 16 + a_ch) * 2);
            #pragma unroll
            for (int np = 0; np < 2; np++)
                ldmx4(wf[np], wb + ((wn * 32 + np * 16 + w_row) * 40 + kk * 16 + w_ch) * 2);
            #pragma unroll
            for (int mi = 0; mi < 4; mi++)
                #pragma unroll
                for (int np = 0; np < 2; np++) {
                    mma16(acc[mi][2 * np],     af[mi], wf[np]);
                    mma16(acc[mi][2 * np + 1], af[mi], wf[np] + 2);
                }
        }
    }

    #pragma unroll
    for (int mi = 0; mi < 4; mi++) {
        #pragma unroll
        for (int ni = 0; ni < 4; ni++) {
            int r = m0 + wm * 64 + mi * 16 + g;
            int c = n0 + wn * 32 + ni * 8 + 2 * t;
            if (OUT_HALF) {
                uint32_t* oh = (uint32_t*)outp;
                oh[(size_t)r * (DMODEL / 2) + (c >> 1)] = h2(acc[mi][ni][0], acc[mi][ni][1]);
                oh[(size_t)(r + 8) * (DMODEL / 2) + (c >> 1)] = h2(acc[mi][ni][2], acc[mi][ni][3]);
            } else {
                float* of = (float*)outp;
                *(float2*)(of + (size_t)r * DMODEL + c) =
                    make_float2(acc[mi][ni][0], acc[mi][ni][1]);
                *(float2*)(of + (size_t)(r + 8) * DMODEL + c) =
                    make_float2(acc[mi][ni][2], acc[mi][ni][3]);
            }
        }
    }
}

// ---------------------------------------------------------------------------
// Attention (fp16): CTA = (b, h, 128 queries), 256 threads / 8 warps x 16q.
// 32 key tiles of 64. SOFTWARE-PIPELINED: iter kt issues S(kt) then PV(kt-1)
// (64 back-to-back HMMA), then computes sigmoid(kt) on the fma/MUFU pipes
// while the tensor pipe drains. pa registers carry P across iterations.
// cp.async: 4 buffers, prefetch distance 2 (V of tile kt-1 must stay live).
// Smem: 4 x (Ks 9216 + Vs 9216) = 73728 B dyn. 2 CTAs/SM.
// ---------------------------------------------------------------------------
__global__ __launch_bounds__(256, 2) void attn_h(
    const __half* __restrict__ Q, const __half* __restrict__ K,
    const __half* __restrict__ V, __half* __restrict__ A)
{
    extern __shared__ uint32_t sm[];
    const uint32_t ksa = smem_u32(sm), vsa = ksa + 36864;

    const int tid = threadIdx.x, wid = tid >> 5, lane = tid & 31;
    const int g = lane >> 2, t = lane & 3;
    const int q0 = blockIdx.x * 128, h = blockIdx.y, b = blockIdx.z;

    // ---- Q A-frags direct from gmem (u32 = half2 along k)
    const uint32_t* Qw = (const uint32_t*)Q +
        ((size_t)(b * SEQ + q0 + wid * 16) * DMODEL + h * DEPTH) / 2;
    uint32_t qf[4][4];
    #pragma unroll
    for (int kk = 0; kk < 4; kk++) {
        qf[kk][0] = Qw[(size_t)g * 256 + kk * 8 + t];
        qf[kk][1] = Qw[(size_t)(g + 8) * 256 + kk * 8 + t];
        qf[kk][2] = Qw[(size_t)g * 256 + kk * 8 + t + 4];
        qf[kk][3] = Qw[(size_t)(g + 8) * 256 + kk * 8 + t + 4];
    }

    const __half* Kg = K + (size_t)(b * SEQ) * DMODEL + h * DEPTH;
    const __half* Vg = V + (size_t)(b * SEQ) * DMODEL + h * DEPTH;

    const int l7 = lane & 7;
    const int k_row = ((lane >> 4) & 1) * 8 + l7, k_ch = ((lane >> 3) & 1) * 8;
    const uint32_t lrow = lane & 15, lhi = (lane >> 4) << 3;

    // ---- prologue: cp tiles 0,1 (prefetch distance 2)
    #pragma unroll
    for (int s = 0; s < 2; s++) {
        #pragma unroll
        for (int j = 0; j < 2; j++) {
            int idx = tid + 256 * j, r = idx >> 3, c = idx & 7;
            cp16(ksa + (s * 2304 + r * 36 + c * 4) * 4, Kg + (size_t)(s * 64 + r) * DMODEL + c * 8);
            cp16(vsa + (s * 2304 + r * 36 + c * 4) * 4, Vg + (size_t)(s * 64 + r) * DMODEL + c * 8);
        }
        CP_COMMIT();
    }

    float o[8][4] = {};
    uint32_t pa[4][4];               // sigmoid(kt) carried to iter kt+1
    const float C1 = 0.18033688f;    // 0.125 * log2(e); bias*log2e = -11 exactly

    for (int kt = 0; kt < 32; kt++) {
        const int buf = kt & 3;
        CP_WAIT1();                  // tile kt landed (kt+1 may be in flight)
        __syncthreads();             // all reads of tile kt-2 (PV at iter kt-1) done
        if (kt + 2 < 32) {
            int b2 = (kt + 2) & 3, r0 = (kt + 2) * 64;
            #pragma unroll
            for (int j = 0; j < 2; j++) {
                int idx = tid + 256 * j, r = idx >> 3, c = idx & 7;
                cp16(ksa + (b2 * 2304 + r * 36 + c * 4) * 4, Kg + (size_t)(r0 + r) * DMODEL + c * 8);
                cp16(vsa + (b2 * 2304 + r * 36 + c * 4) * 4, Vg + (size_t)(r0 + r) * DMODEL + c * 8);
            }
        }
        CP_COMMIT();

        const uint32_t kb_base = ksa + buf * 9216;   // bytes

        // ---- S = Q K^T (tile kt): 32 HMMA
        float s[8][4] = {};
        #pragma unroll
        for (int kk = 0; kk < 4; kk++) {
            #pragma unroll
            for (int np = 0; np < 4; np++) {
                uint32_t kb[4];
                ldmx4(kb, kb_base + ((np * 16 + k_row) * 72 + kk * 16 + k_ch) * 2);
                mma16(s[2 * np],     qf[kk], kb);
                mma16(s[2 * np + 1], qf[kk], kb + 2);
            }
        }

        // ---- PV (tile kt-1): 32 more HMMA, independent of S/sigmoid above
        if (kt > 0) {
            const uint32_t vb_prev = vsa + ((kt - 1) & 3) * 9216;
            #pragma unroll
            for (int kkv = 0; kkv < 4; kkv++) {
                #pragma unroll
                for (int j = 0; j < 4; j++) {
                    uint32_t vb[4];
                    ldmx4t(vb, vb_prev + ((kkv * 16 + lrow) * 72 + j * 16 + lhi) * 2);
                    mma16(o[2 * j],     pa[kkv], vb);
                    mma16(o[2 * j + 1], pa[kkv], vb + 2);
                }
            }
        }

        // ---- sigmoid(kt) on fma/MUFU pipes while tensor drains PV/S
        #pragma unroll
        for (int nb = 0; nb < 8; nb++) {
            float p[4];
            #pragma unroll
            for (int e = 0; e < 4; e++) {
                float y = ex2f(s[nb][e] * C1 - 11.0f);
                p[e] = y * (1.0f - y) * (1.0f + y * y);
            }
            int kkv = nb >> 1, hf = (nb & 1) << 1;
            pa[kkv][hf]     = h2(p[0], p[1]);
            pa[kkv][hf + 1] = h2(p[2], p[3]);
        }
    }

    // ---- epilogue: PV(31)
    {
        const uint32_t vb_prev = vsa + (31 & 3) * 9216;
        #pragma unroll
        for (int kkv = 0; kkv < 4; kkv++) {
            #pragma unroll
            for (int j = 0; j < 4; j++) {
                uint32_t vb[4];
                ldmx4t(vb, vb_prev + ((kkv * 16 + lrow) * 72 + j * 16 + lhi) * 2);
                mma16(o[2 * j],     pa[kkv], vb);
                mma16(o[2 * j + 1], pa[kkv], vb + 2);
            }
        }
    }

    // ---- write O tile (fp16, 16q x 64d per warp)
    uint32_t* Aw = (uint32_t*)A +
        ((size_t)(b * SEQ + q0 + wid * 16) * DMODEL + h * DEPTH) / 2;
    #pragma unroll
    for (int nb = 0; nb < 8; nb++) {
        Aw[(size_t)g * 256 + nb * 4 + t]       = h2(o[nb][0], o[nb][1]);
        Aw[(size_t)(g + 8) * 256 + nb * 4 + t] = h2(o[nb][2], o[nb][3]);
    }
}

// ---------------------------------------------------------------------------
extern "C" void kernel_launch(void* const* d_in, const int* in_sizes, int n_in,
                              void* d_out, int out_size) {
    const float* x  = (const float*)d_in[0];
    const float* Wq = (const float*)d_in[1];
    const float* Wk = (const float*)d_in[2];
    const float* Wv = (const float*)d_in[3];
    const float* Wo = (const float*)d_in[4];
    float* out = (float*)d_out;

    __half *xh, *Wh, *Qh, *Kh, *Vh, *Ah;
    cudaGetSymbolAddress((void**)&xh, g_xh);
    cudaGetSymbolAddress((void**)&Wh, g_Wh);
    cudaGetSymbolAddress((void**)&Qh, g_Qh);
    cudaGetSymbolAddress((void**)&Kh, g_Kh);
    cudaGetSymbolAddress((void**)&Vh, g_Vh);
    cudaGetSymbolAddress((void**)&Ah, g_Ah);

    const int GSM = 81920, ASM = 73728;
    cudaFuncSetAttribute(gemm_h<1>, cudaFuncAttributeMaxDynamicSharedMemorySize, GSM);
    cudaFuncSetAttribute(gemm_h<0>, cudaFuncAttributeMaxDynamicSharedMemorySize, GSM);
    cudaFuncSetAttribute(attn_h,    cudaFuncAttributeMaxDynamicSharedMemorySize, ASM);

    const int n_total = (MROWS * DMODEL + 4 * DMODEL * DMODEL) / 4;
    cvt_all<<<(n_total + 255) / 256, 256>>>(
        (const float4*)x, (const float4*)Wq, (const float4*)Wk,
        (const float4*)Wv, (const float4*)Wo, (uint2*)xh, (uint2*)Wh);

    dim3 gq(12, MROWS / 128);            // fused QKV: 768 CTAs
    dim3 go(4, MROWS / 128);             // Wo: 256 CTAs
    dim3 ga(SEQ / 128, HEADS, BATCH);    // 512 CTAs

    gemm_h<1><<<gq, 256, GSM>>>(xh, Wh, Qh, Kh, Vh);
    attn_h<<<ga, 256, ASM>>>(Qh, Kh, Vh, Ah);
    gemm_h<0><<<go, 256, GSM>>>(Ah, Wh + 3 * WSZ, out, out, out);
}

// round 13
// speedup vs baseline: 1.0819x; 1.0819x over previous
#include <cuda_runtime.h>
#include <cuda_fp16.h>
#include <cstdint>

#define BATCH  4
#define SEQ    2048
#define HEADS  8
#define DEPTH  64
#define DMODEL 512
#define MROWS  (BATCH*SEQ)   // 8192
#define WSZ    ((size_t)DMODEL * DMODEL)

// fp16 scratch (allocation-free rule: __device__ globals)
__device__ __half g_xh[MROWS * DMODEL];
__device__ __half g_Wh[4 * DMODEL * DMODEL];   // Wq, Wk, Wv, Wo
__device__ __half g_Qh[MROWS * DMODEL];
__device__ __half g_Kh[MROWS * DMODEL];
__device__ __half g_Vh[MROWS * DMODEL];
__device__ __half g_Ah[MROWS * DMODEL];

// ---------------- helpers ----------------
__device__ __forceinline__ uint32_t h2(float lo, float hi) {
    uint32_t r;
    asm("cvt.rn.f16x2.f32 %0, %1, %2;" : "=r"(r) : "f"(hi), "f"(lo));
    return r;
}
__device__ __forceinline__ void mma16(float* d, const uint32_t* a, const uint32_t* b) {
    asm volatile(
        "mma.sync.aligned.m16n8k16.row.col.f32.f16.f16.f32 "
        "{%0,%1,%2,%3}, {%4,%5,%6,%7}, {%8,%9}, {%0,%1,%2,%3};"
        : "+f"(d[0]), "+f"(d[1]), "+f"(d[2]), "+f"(d[3])
        : "r"(a[0]), "r"(a[1]), "r"(a[2]), "r"(a[3]), "r"(b[0]), "r"(b[1]));
}
__device__ __forceinline__ float ex2f(float x) {
    float r; asm("ex2.approx.f32 %0, %1;" : "=f"(r) : "f"(x));
    return r;
}
__device__ __forceinline__ uint32_t smem_u32(const void* p) {
    uint32_t a;
    asm("{ .reg .u64 t; cvta.to.shared.u64 t, %1; cvt.u32.u64 %0, t; }" : "=r"(a) : "l"(p));
    return a;
}
__device__ __forceinline__ void ldmx4(uint32_t* r, uint32_t addr) {   // non-trans
    asm volatile(
        "ldmatrix.sync.aligned.m8n8.x4.shared.b16 {%0,%1,%2,%3}, [%4];"
        : "=r"(r[0]), "=r"(r[1]), "=r"(r[2]), "=r"(r[3]) : "r"(addr));
}
__device__ __forceinline__ void ldmx4t(uint32_t* r, uint32_t addr) {  // transposed
    asm volatile(
        "ldmatrix.sync.aligned.m8n8.x4.trans.shared.b16 {%0,%1,%2,%3}, [%4];"
        : "=r"(r[0]), "=r"(r[1]), "=r"(r[2]), "=r"(r[3]) : "r"(addr));
}
__device__ __forceinline__ void cp16(uint32_t dst, const void* src) {
    asm volatile("cp.async.cg.shared.global [%0], [%1], 16;" :: "r"(dst), "l"(src));
}
#define CP_COMMIT() asm volatile("cp.async.commit_group;" ::: "memory")
#define CP_WAIT1()  asm volatile("cp.async.wait_group 1;" ::: "memory")
#define CP_WAIT2()  asm volatile("cp.async.wait_group 2;" ::: "memory")

// ---------------------------------------------------------------------------
// fused fp32 -> fp16 conversion: x + 4 weights in ONE launch
// ---------------------------------------------------------------------------
__global__ void cvt_all(
    const float4* __restrict__ x,
    const float4* __restrict__ w0, const float4* __restrict__ w1,
    const float4* __restrict__ w2, const float4* __restrict__ w3,
    uint2* __restrict__ xh, uint2* __restrict__ wh)
{
    const int n4x = MROWS * DMODEL / 4;
    const int n4w = DMODEL * DMODEL / 4;
    int i = blockIdx.x * blockDim.x + threadIdx.x;
    if (i < n4x) {
        float4 v = x[i];
        xh[i] = make_uint2(h2(v.x, v.y), h2(v.z, v.w));
    } else {
        int j = i - n4x;
        if (j < 4 * n4w) {
            int sel = j / n4w, r = j - sel * n4w;
            const float4* s = sel == 0 ? w0 : (sel == 1 ? w1 : (sel == 2 ? w2 : w3));
            float4 v = s[r];
            wh[j] = make_uint2(h2(v.x, v.y), h2(v.z, v.w));
        }
    }
}

// ---------------------------------------------------------------------------
// GEMM: out[m][n] = sum_k A[m][k] * W[n][k]   (fp16 in, fp32 accum)
// CTA 128x128, 8 warps (2M x 4N), warp 64x32. BK=64: 8 chunk iterations,
// 4 unbroken kk-steps per barrier window. cp.async 3-stage.
// Smem rows: 32 data u32 + 4 pad (stride 36). Stage = 18432 B/matrix.
// dyn smem = 3*2*18432 = 110592 B -> 2 CTAs/SM. bx>>2 picks W/out (fused QKV).
// ---------------------------------------------------------------------------
template<int OUT_HALF>
__global__ __launch_bounds__(256, 2) void gemm_h(
    const __half* __restrict__ A, const __half* __restrict__ W,
    void* __restrict__ O0, void* __restrict__ O1, void* __restrict__ O2)
{
    extern __shared__ uint32_t sm[];
    const uint32_t asa = smem_u32(sm), wsa = asa + 55296;

    const int tid = threadIdx.x, wid = tid >> 5, lane = tid & 31;
    const int g = lane >> 2, t = lane & 3;
    const int wm = wid & 1, wn = wid >> 1;
    const int bx = blockIdx.x;
    const int sel = bx >> 2, n0 = (bx & 3) << 7;
    const int m0 = blockIdx.y * 128;
    void* outp = sel == 0 ? O0 : (sel == 1 ? O1 : O2);

    const __half* Ab = A + (size_t)m0 * DMODEL;
    const __half* Wb = W + (size_t)sel * WSZ + (size_t)n0 * DMODEL;

    const int l7 = lane & 7;
    const int a_row = ((lane >> 3) & 1) * 8 + l7, a_ch = ((lane >> 4) & 1) * 8;
    const int w_row = ((lane >> 4) & 1) * 8 + l7, w_ch = ((lane >> 3) & 1) * 8;

    // prologue: chunks 0,1 (each chunk = 128 rows x 64 halves per matrix)
    #pragma unroll
    for (int s = 0; s < 2; s++) {
        #pragma unroll
        for (int j = 0; j < 4; j++) {
            int idx = tid + 256 * j, r = idx >> 3, c = idx & 7;
            cp16(asa + (s * 4608 + r * 36 + c * 4) * 4, Ab + (size_t)r * DMODEL + s * 64 + c * 8);
            cp16(wsa + (s * 4608 + r * 36 + c * 4) * 4, Wb + (size_t)r * DMODEL + s * 64 + c * 8);
        }
        CP_COMMIT();
    }

    float acc[4][4][4] = {};

    for (int kc = 0; kc < 8; kc++) {
        const int buf = kc % 3;
        CP_WAIT1();
        __syncthreads();
        if (kc + 2 < 8) {
            int b2 = (kc + 2) % 3, k0 = (kc + 2) * 64;
            #pragma unroll
            for (int j = 0; j < 4; j++) {
                int idx = tid + 256 * j, r = idx >> 3, c = idx & 7;
                cp16(asa + (b2 * 4608 + r * 36 + c * 4) * 4, Ab + (size_t)r * DMODEL + k0 + c * 8);
                cp16(wsa + (b2 * 4608 + r * 36 + c * 4) * 4, Wb + (size_t)r * DMODEL + k0 + c * 8);
            }
        }
        CP_COMMIT();

        const uint32_t ab = asa + buf * 18432;   // bytes
        const uint32_t wb = wsa + buf * 18432;
        #pragma unroll
        for (int kk = 0; kk < 4; kk++) {
            uint32_t af[4][4], wf[2][4];
            #pragma unroll
            for (int mi = 0; mi < 4; mi++)
                ldmx4(af[mi], ab + ((wm * 64 + mi * 16 + a_row) * 72 + kk * 16 + a_ch) * 2);
            #pragma unroll
            for (int np = 0; np < 2; np++)
                ldmx4(wf[np], wb + ((wn * 32 + np * 16 + w_row) * 72 + kk * 16 + w_ch) * 2);
            #pragma unroll
            for (int mi = 0; mi < 4; mi++)
                #pragma unroll
                for (int np = 0; np < 2; np++) {
                    mma16(acc[mi][2 * np],     af[mi], wf[np]);
                    mma16(acc[mi][2 * np + 1], af[mi], wf[np] + 2);
                }
        }
    }

    #pragma unroll
    for (int mi = 0; mi < 4; mi++) {
        #pragma unroll
        for (int ni = 0; ni < 4; ni++) {
            int r = m0 + wm * 64 + mi * 16 + g;
            int c = n0 + wn * 32 + ni * 8 + 2 * t;
            if (OUT_HALF) {
                uint32_t* oh = (uint32_t*)outp;
                oh[(size_t)r * (DMODEL / 2) + (c >> 1)] = h2(acc[mi][ni][0], acc[mi][ni][1]);
                oh[(size_t)(r + 8) * (DMODEL / 2) + (c >> 1)] = h2(acc[mi][ni][2], acc[mi][ni][3]);
            } else {
                float* of = (float*)outp;
                *(float2*)(of + (size_t)r * DMODEL + c) =
                    make_float2(acc[mi][ni][0], acc[mi][ni][1]);
                *(float2*)(of + (size_t)(r + 8) * DMODEL + c) =
                    make_float2(acc[mi][ni][2], acc[mi][ni][3]);
            }
        }
    }
}

// ---------------------------------------------------------------------------
// Attention (fp16): CTA = (b, h, 128 queries), 256 threads / 8 warps x 16q.
// 32 key tiles of 64, cp.async 4-stage, prefetch distance 3 (R10 pipeline).
// HALF-TILE INTERLEAVE inside the iteration: S_A(keys 0:31) -> S_B(32:63)
// -> sigmoid_A (overlaps S_B drain) -> PV_A -> sigmoid_B (overlaps PV_A)
// -> PV_B. No cross-iteration register state (unlike failed R12).
// Smem: 4 x (Ks 9216 + Vs 9216) = 73728 B dyn. 2 CTAs/SM.
// ---------------------------------------------------------------------------
__global__ __launch_bounds__(256, 2) void attn_h(
    const __half* __restrict__ Q, const __half* __restrict__ K,
    const __half* __restrict__ V, __half* __restrict__ A)
{
    extern __shared__ uint32_t sm[];
    const uint32_t ksa = smem_u32(sm), vsa = ksa + 36864;

    const int tid = threadIdx.x, wid = tid >> 5, lane = tid & 31;
    const int g = lane >> 2, t = lane & 3;
    const int q0 = blockIdx.x * 128, h = blockIdx.y, b = blockIdx.z;

    // ---- Q A-frags direct from gmem (u32 = half2 along k)
    const uint32_t* Qw = (const uint32_t*)Q +
        ((size_t)(b * SEQ + q0 + wid * 16) * DMODEL + h * DEPTH) / 2;
    uint32_t qf[4][4];
    #pragma unroll
    for (int kk = 0; kk < 4; kk++) {
        qf[kk][0] = Qw[(size_t)g * 256 + kk * 8 + t];
        qf[kk][1] = Qw[(size_t)(g + 8) * 256 + kk * 8 + t];
        qf[kk][2] = Qw[(size_t)g * 256 + kk * 8 + t + 4];
        qf[kk][3] = Qw[(size_t)(g + 8) * 256 + kk * 8 + t + 4];
    }

    const __half* Kg = K + (size_t)(b * SEQ) * DMODEL + h * DEPTH;
    const __half* Vg = V + (size_t)(b * SEQ) * DMODEL + h * DEPTH;

    const int l7 = lane & 7;
    const int k_row = ((lane >> 4) & 1) * 8 + l7, k_ch = ((lane >> 3) & 1) * 8;
    const uint32_t lrow = lane & 15, lhi = (lane >> 4) << 3;

    // ---- prologue: cp tiles 0..2
    #pragma unroll
    for (int s = 0; s < 3; s++) {
        #pragma unroll
        for (int j = 0; j < 2; j++) {
            int idx = tid + 256 * j, r = idx >> 3, c = idx & 7;
            cp16(ksa + (s * 2304 + r * 36 + c * 4) * 4, Kg + (size_t)(s * 64 + r) * DMODEL + c * 8);
            cp16(vsa + (s * 2304 + r * 36 + c * 4) * 4, Vg + (size_t)(s * 64 + r) * DMODEL + c * 8);
        }
        CP_COMMIT();
    }

    float o[8][4] = {};
    const float C1 = 0.18033688f;   // 0.125 * log2(e); bias*log2e = -11 exactly

    for (int kt = 0; kt < 32; kt++) {
        const int buf = kt & 3;
        CP_WAIT2();
        __syncthreads();
        if (kt + 3 < 32) {
            int b2 = (kt + 3) & 3, r0 = (kt + 3) * 64;
            #pragma unroll
            for (int j = 0; j < 2; j++) {
                int idx = tid + 256 * j, r = idx >> 3, c = idx & 7;
                cp16(ksa + (b2 * 2304 + r * 36 + c * 4) * 4, Kg + (size_t)(r0 + r) * DMODEL + c * 8);
                cp16(vsa + (b2 * 2304 + r * 36 + c * 4) * 4, Vg + (size_t)(r0 + r) * DMODEL + c * 8);
            }
        }
        CP_COMMIT();

        const uint32_t kb_base = ksa + buf * 9216;   // bytes
        const uint32_t vb_base = vsa + buf * 9216;

        // ---- S_A: keys 0:31 (np=0,1) -> s[0..3]
        float s[8][4] = {};
        #pragma unroll
        for (int kk = 0; kk < 4; kk++) {
            #pragma unroll
            for (int np = 0; np < 2; np++) {
                uint32_t kb[4];
                ldmx4(kb, kb_base + ((np * 16 + k_row) * 72 + kk * 16 + k_ch) * 2);
                mma16(s[2 * np],     qf[kk], kb);
                mma16(s[2 * np + 1], qf[kk], kb + 2);
            }
        }
        // ---- S_B: keys 32:63 (np=2,3) -> s[4..7]
        #pragma unroll
        for (int kk = 0; kk < 4; kk++) {
            #pragma unroll
            for (int np = 2; np < 4; np++) {
                uint32_t kb[4];
                ldmx4(kb, kb_base + ((np * 16 + k_row) * 72 + kk * 16 + k_ch) * 2);
                mma16(s[2 * np],     qf[kk], kb);
                mma16(s[2 * np + 1], qf[kk], kb + 2);
            }
        }

        // ---- sigmoid_A (fma/MUFU; overlaps S_B tensor drain)
        uint32_t paA[2][4];
        #pragma unroll
        for (int nb = 0; nb < 4; nb++) {
            float p[4];
            #pragma unroll
            for (int e = 0; e < 4; e++) {
                float y = ex2f(s[nb][e] * C1 - 11.0f);
                p[e] = y * (1.0f - y) * (1.0f + y * y);
            }
            int kkv = nb >> 1, hf = (nb & 1) << 1;
            paA[kkv][hf]     = h2(p[0], p[1]);
            paA[kkv][hf + 1] = h2(p[2], p[3]);
        }

        // ---- PV_A: keys 0:31 (kkv=0,1)
        #pragma unroll
        for (int kkv = 0; kkv < 2; kkv++) {
            #pragma unroll
            for (int j = 0; j < 4; j++) {
                uint32_t vb[4];
                ldmx4t(vb, vb_base + ((kkv * 16 + lrow) * 72 + j * 16 + lhi) * 2);
                mma16(o[2 * j],     paA[kkv], vb);
                mma16(o[2 * j + 1], paA[kkv], vb + 2);
            }
        }

        // ---- sigmoid_B (overlaps PV_A tensor occupancy)
        uint32_t paB[2][4];
        #pragma unroll
        for (int nb = 4; nb < 8; nb++) {
            float p[4];
            #pragma unroll
            for (int e = 0; e < 4; e++) {
                float y = ex2f(s[nb][e] * C1 - 11.0f);
                p[e] = y * (1.0f - y) * (1.0f + y * y);
            }
            int kkv = (nb - 4) >> 1, hf = (nb & 1) << 1;
            paB[kkv][hf]     = h2(p[0], p[1]);
            paB[kkv][hf + 1] = h2(p[2], p[3]);
        }

        // ---- PV_B: keys 32:63 (kkv=2,3)
        #pragma unroll
        for (int kkv = 2; kkv < 4; kkv++) {
            #pragma unroll
            for (int j = 0; j < 4; j++) {
                uint32_t vb[4];
                ldmx4t(vb, vb_base + ((kkv * 16 + lrow) * 72 + j * 16 + lhi) * 2);
                mma16(o[2 * j],     paB[kkv - 2], vb);
                mma16(o[2 * j + 1], paB[kkv - 2], vb + 2);
            }
        }
    }

    // ---- write O tile (fp16, 16q x 64d per warp)
    uint32_t* Aw = (uint32_t*)A +
        ((size_t)(b * SEQ + q0 + wid * 16) * DMODEL + h * DEPTH) / 2;
    #pragma unroll
    for (int nb = 0; nb < 8; nb++) {
        Aw[(size_t)g * 256 + nb * 4 + t]       = h2(o[nb][0], o[nb][1]);
        Aw[(size_t)(g + 8) * 256 + nb * 4 + t] = h2(o[nb][2], o[nb][3]);
    }
}

// ---------------------------------------------------------------------------
extern "C" void kernel_launch(void* const* d_in, const int* in_sizes, int n_in,
                              void* d_out, int out_size) {
    const float* x  = (const float*)d_in[0];
    const float* Wq = (const float*)d_in[1];
    const float* Wk = (const float*)d_in[2];
    const float* Wv = (const float*)d_in[3];
    const float* Wo = (const float*)d_in[4];
    float* out = (float*)d_out;

    __half *xh, *Wh, *Qh, *Kh, *Vh, *Ah;
    cudaGetSymbolAddress((void**)&xh, g_xh);
    cudaGetSymbolAddress((void**)&Wh, g_Wh);
    cudaGetSymbolAddress((void**)&Qh, g_Qh);
    cudaGetSymbolAddress((void**)&Kh, g_Kh);
    cudaGetSymbolAddress((void**)&Vh, g_Vh);
    cudaGetSymbolAddress((void**)&Ah, g_Ah);

    const int GSM = 110592, ASM = 73728;
    cudaFuncSetAttribute(gemm_h<1>, cudaFuncAttributeMaxDynamicSharedMemorySize, GSM);
    cudaFuncSetAttribute(gemm_h<0>, cudaFuncAttributeMaxDynamicSharedMemorySize, GSM);
    cudaFuncSetAttribute(attn_h,    cudaFuncAttributeMaxDynamicSharedMemorySize, ASM);

    const int n_total = (MROWS * DMODEL + 4 * DMODEL * DMODEL) / 4;
    cvt_all<<<(n_total + 255) / 256, 256>>>(
        (const float4*)x, (const float4*)Wq, (const float4*)Wk,
        (const float4*)Wv, (const float4*)Wo, (uint2*)xh, (uint2*)Wh);

    dim3 gq(12, MROWS / 128);            // fused QKV: 768 CTAs
    dim3 go(4, MROWS / 128);             // Wo: 256 CTAs
    dim3 ga(SEQ / 128, HEADS, BATCH);    // 512 CTAs

    gemm_h<1><<<gq, 256, GSM>>>(xh, Wh, Qh, Kh, Vh);
    attn_h<<<ga, 256, ASM>>>(Qh, Kh, Vh, Ah);
    gemm_h<0><<<go, 256, GSM>>>(Ah, Wh + 3 * WSZ, out, out, out);
}

// round 14
// speedup vs baseline: 1.1598x; 1.0720x over previous
#include <cuda_runtime.h>
#include <cuda_fp16.h>
#include <cstdint>

#define BATCH  4
#define SEQ    2048
#define HEADS  8
#define DEPTH  64
#define DMODEL 512
#define MROWS  (BATCH*SEQ)   // 8192
#define WSZ    ((size_t)DMODEL * DMODEL)

// fp16 scratch (allocation-free rule: __device__ globals)
__device__ __half g_xh[MROWS * DMODEL];
__device__ __half g_Wh[4 * DMODEL * DMODEL];   // Wq, Wk, Wv, Wo
__device__ __half g_Qh[MROWS * DMODEL];
__device__ __half g_Kh[MROWS * DMODEL];
__device__ __half g_Vh[MROWS * DMODEL];
__device__ __half g_Ah[MROWS * DMODEL];

// ---------------- helpers ----------------
__device__ __forceinline__ uint32_t h2(float lo, float hi) {
    uint32_t r;
    asm("cvt.rn.f16x2.f32 %0, %1, %2;" : "=r"(r) : "f"(hi), "f"(lo));
    return r;
}
__device__ __forceinline__ void mma16(float* d, const uint32_t* a, const uint32_t* b) {
    asm volatile(
        "mma.sync.aligned.m16n8k16.row.col.f32.f16.f16.f32 "
        "{%0,%1,%2,%3}, {%4,%5,%6,%7}, {%8,%9}, {%0,%1,%2,%3};"
        : "+f"(d[0]), "+f"(d[1]), "+f"(d[2]), "+f"(d[3])
        : "r"(a[0]), "r"(a[1]), "r"(a[2]), "r"(a[3]), "r"(b[0]), "r"(b[1]));
}
__device__ __forceinline__ float ex2f(float x) {
    float r; asm("ex2.approx.f32 %0, %1;" : "=f"(r) : "f"(x));
    return r;
}
__device__ __forceinline__ uint32_t smem_u32(const void* p) {
    uint32_t a;
    asm("{ .reg .u64 t; cvta.to.shared.u64 t, %1; cvt.u32.u64 %0, t; }" : "=r"(a) : "l"(p));
    return a;
}
__device__ __forceinline__ void ldmx4(uint32_t* r, uint32_t addr) {   // non-trans
    asm volatile(
        "ldmatrix.sync.aligned.m8n8.x4.shared.b16 {%0,%1,%2,%3}, [%4];"
        : "=r"(r[0]), "=r"(r[1]), "=r"(r[2]), "=r"(r[3]) : "r"(addr));
}
__device__ __forceinline__ void ldmx4t(uint32_t* r, uint32_t addr) {  // transposed
    asm volatile(
        "ldmatrix.sync.aligned.m8n8.x4.trans.shared.b16 {%0,%1,%2,%3}, [%4];"
        : "=r"(r[0]), "=r"(r[1]), "=r"(r[2]), "=r"(r[3]) : "r"(addr));
}
__device__ __forceinline__ void cp16(uint32_t dst, const void* src) {
    asm volatile("cp.async.cg.shared.global [%0], [%1], 16;" :: "r"(dst), "l"(src));
}
#define CP_COMMIT() asm volatile("cp.async.commit_group;" ::: "memory")
#define CP_WAIT1()  asm volatile("cp.async.wait_group 1;" ::: "memory")

// ---------------------------------------------------------------------------
// fused fp32 -> fp16 conversion: x + 4 weights in ONE launch
// ---------------------------------------------------------------------------
__global__ void cvt_all(
    const float4* __restrict__ x,
    const float4* __restrict__ w0, const float4* __restrict__ w1,
    const float4* __restrict__ w2, const float4* __restrict__ w3,
    uint2* __restrict__ xh, uint2* __restrict__ wh)
{
    const int n4x = MROWS * DMODEL / 4;
    const int n4w = DMODEL * DMODEL / 4;
    int i = blockIdx.x * blockDim.x + threadIdx.x;
    if (i < n4x) {
        float4 v = x[i];
        xh[i] = make_uint2(h2(v.x, v.y), h2(v.z, v.w));
    } else {
        int j = i - n4x;
        if (j < 4 * n4w) {
            int sel = j / n4w, r = j - sel * n4w;
            const float4* s = sel == 0 ? w0 : (sel == 1 ? w1 : (sel == 2 ? w2 : w3));
            float4 v = s[r];
            wh[j] = make_uint2(h2(v.x, v.y), h2(v.z, v.w));
        }
    }
}

// ---------------------------------------------------------------------------
// GEMM: out[m][n] = sum_k A[m][k] * W[n][k]   (fp16 in, fp32 accum)
// CTA 128x128, 8 warps (2M x 4N), warp 64x32. BK=64: 8 chunk iterations.
// cp.async 3-stage. dyn smem = 110592 B -> 2 CTAs/SM. bx>>2 picks W/out.
// ---------------------------------------------------------------------------
template<int OUT_HALF>
__global__ __launch_bounds__(256, 2) void gemm_h(
    const __half* __restrict__ A, const __half* __restrict__ W,
    void* __restrict__ O0, void* __restrict__ O1, void* __restrict__ O2)
{
    extern __shared__ uint32_t sm[];
    const uint32_t asa = smem_u32(sm), wsa = asa + 55296;

    const int tid = threadIdx.x, wid = tid >> 5, lane = tid & 31;
    const int g = lane >> 2, t = lane & 3;
    const int wm = wid & 1, wn = wid >> 1;
    const int bx = blockIdx.x;
    const int sel = bx >> 2, n0 = (bx & 3) << 7;
    const int m0 = blockIdx.y * 128;
    void* outp = sel == 0 ? O0 : (sel == 1 ? O1 : O2);

    const __half* Ab = A + (size_t)m0 * DMODEL;
    const __half* Wb = W + (size_t)sel * WSZ + (size_t)n0 * DMODEL;

    const int l7 = lane & 7;
    const int a_row = ((lane >> 3) & 1) * 8 + l7, a_ch = ((lane >> 4) & 1) * 8;
    const int w_row = ((lane >> 4) & 1) * 8 + l7, w_ch = ((lane >> 3) & 1) * 8;

    // prologue: chunks 0,1
    #pragma unroll
    for (int s = 0; s < 2; s++) {
        #pragma unroll
        for (int j = 0; j < 4; j++) {
            int idx = tid + 256 * j, r = idx >> 3, c = idx & 7;
            cp16(asa + (s * 4608 + r * 36 + c * 4) * 4, Ab + (size_t)r * DMODEL + s * 64 + c * 8);
            cp16(wsa + (s * 4608 + r * 36 + c * 4) * 4, Wb + (size_t)r * DMODEL + s * 64 + c * 8);
        }
        CP_COMMIT();
    }

    float acc[4][4][4] = {};

    for (int kc = 0; kc < 8; kc++) {
        const int buf = kc % 3;
        CP_WAIT1();
        __syncthreads();
        if (kc + 2 < 8) {
            int b2 = (kc + 2) % 3, k0 = (kc + 2) * 64;
            #pragma unroll
            for (int j = 0; j < 4; j++) {
                int idx = tid + 256 * j, r = idx >> 3, c = idx & 7;
                cp16(asa + (b2 * 4608 + r * 36 + c * 4) * 4, Ab + (size_t)r * DMODEL + k0 + c * 8);
                cp16(wsa + (b2 * 4608 + r * 36 + c * 4) * 4, Wb + (size_t)r * DMODEL + k0 + c * 8);
            }
        }
        CP_COMMIT();

        const uint32_t ab = asa + buf * 18432;   // bytes
        const uint32_t wb = wsa + buf * 18432;
        #pragma unroll
        for (int kk = 0; kk < 4; kk++) {
            uint32_t af[4][4], wf[2][4];
            #pragma unroll
            for (int mi = 0; mi < 4; mi++)
                ldmx4(af[mi], ab + ((wm * 64 + mi * 16 + a_row) * 72 + kk * 16 + a_ch) * 2);
            #pragma unroll
            for (int np = 0; np < 2; np++)
                ldmx4(wf[np], wb + ((wn * 32 + np * 16 + w_row) * 72 + kk * 16 + w_ch) * 2);
            #pragma unroll
            for (int mi = 0; mi < 4; mi++)
                #pragma unroll
                for (int np = 0; np < 2; np++) {
                    mma16(acc[mi][2 * np],     af[mi], wf[np]);
                    mma16(acc[mi][2 * np + 1], af[mi], wf[np] + 2);
                }
        }
    }

    #pragma unroll
    for (int mi = 0; mi < 4; mi++) {
        #pragma unroll
        for (int ni = 0; ni < 4; ni++) {
            int r = m0 + wm * 64 + mi * 16 + g;
            int c = n0 + wn * 32 + ni * 8 + 2 * t;
            if (OUT_HALF) {
                uint32_t* oh = (uint32_t*)outp;
                oh[(size_t)r * (DMODEL / 2) + (c >> 1)] = h2(acc[mi][ni][0], acc[mi][ni][1]);
                oh[(size_t)(r + 8) * (DMODEL / 2) + (c >> 1)] = h2(acc[mi][ni][2], acc[mi][ni][3]);
            } else {
                float* of = (float*)outp;
                *(float2*)(of + (size_t)r * DMODEL + c) =
                    make_float2(acc[mi][ni][0], acc[mi][ni][1]);
                *(float2*)(of + (size_t)(r + 8) * DMODEL + c) =
                    make_float2(acc[mi][ni][2], acc[mi][ni][3]);
            }
        }
    }
}

// ---------------------------------------------------------------------------
// Attention (fp16): CTA = (b, h, 64 queries), 128 threads / 4 warps x 16q.
// 4 CTAs/SM (regs 128, smem 55296 B) -> 4 independent barrier domains:
// when one CTA waits on cp.async/BAR, three others issue HMMA.
// 32 key tiles of 64; 3-stage cp.async, prefetch distance 2.
// Body = R13 half-tile interleave (S_A,S_B,sigmoid_A,PV_A,sigmoid_B,PV_B).
// ---------------------------------------------------------------------------
__global__ __launch_bounds__(128, 4) void attn_h(
    const __half* __restrict__ Q, const __half* __restrict__ K,
    const __half* __restrict__ V, __half* __restrict__ A)
{
    extern __shared__ uint32_t sm[];
    const uint32_t ksa = smem_u32(sm), vsa = ksa + 27648;   // 3 x 9216 B each

    const int tid = threadIdx.x, wid = tid >> 5, lane = tid & 31;
    const int g = lane >> 2, t = lane & 3;
    const int q0 = blockIdx.x * 64, h = blockIdx.y, b = blockIdx.z;

    // ---- Q A-frags direct from gmem (u32 = half2 along k)
    const uint32_t* Qw = (const uint32_t*)Q +
        ((size_t)(b * SEQ + q0 + wid * 16) * DMODEL + h * DEPTH) / 2;
    uint32_t qf[4][4];
    #pragma unroll
    for (int kk = 0; kk < 4; kk++) {
        qf[kk][0] = Qw[(size_t)g * 256 + kk * 8 + t];
        qf[kk][1] = Qw[(size_t)(g + 8) * 256 + kk * 8 + t];
        qf[kk][2] = Qw[(size_t)g * 256 + kk * 8 + t + 4];
        qf[kk][3] = Qw[(size_t)(g + 8) * 256 + kk * 8 + t + 4];
    }

    const __half* Kg = K + (size_t)(b * SEQ) * DMODEL + h * DEPTH;
    const __half* Vg = V + (size_t)(b * SEQ) * DMODEL + h * DEPTH;

    const int l7 = lane & 7;
    const int k_row = ((lane >> 4) & 1) * 8 + l7, k_ch = ((lane >> 3) & 1) * 8;
    const uint32_t lrow = lane & 15, lhi = (lane >> 4) << 3;

    // ---- prologue: cp tiles 0,1 (128 threads: 4 iters per matrix)
    #pragma unroll
    for (int s = 0; s < 2; s++) {
        #pragma unroll
        for (int j = 0; j < 4; j++) {
            int idx = tid + 128 * j, r = idx >> 3, c = idx & 7;
            cp16(ksa + (s * 2304 + r * 36 + c * 4) * 4, Kg + (size_t)(s * 64 + r) * DMODEL + c * 8);
            cp16(vsa + (s * 2304 + r * 36 + c * 4) * 4, Vg + (size_t)(s * 64 + r) * DMODEL + c * 8);
        }
        CP_COMMIT();
    }

    float o[8][4] = {};
    const float C1 = 0.18033688f;   // 0.125 * log2(e); bias*log2e = -11 exactly

    for (int kt = 0; kt < 32; kt++) {
        const int buf = kt % 3;
        CP_WAIT1();                  // tile kt landed (kt+1 in flight)
        __syncthreads();             // reads of tile kt-1's slot (done at iter kt-1) sealed
        if (kt + 2 < 32) {
            int b2 = (kt + 2) % 3, r0 = (kt + 2) * 64;
            #pragma unroll
            for (int j = 0; j < 4; j++) {
                int idx = tid + 128 * j, r = idx >> 3, c = idx & 7;
                cp16(ksa + (b2 * 2304 + r * 36 + c * 4) * 4, Kg + (size_t)(r0 + r) * DMODEL + c * 8);
                cp16(vsa + (b2 * 2304 + r * 36 + c * 4) * 4, Vg + (size_t)(r0 + r) * DMODEL + c * 8);
            }
        }
        CP_COMMIT();

        const uint32_t kb_base = ksa + buf * 9216;   // bytes
        const uint32_t vb_base = vsa + buf * 9216;

        // ---- S_A: keys 0:31 (np=0,1) -> s[0..3]
        float s[8][4] = {};
        #pragma unroll
        for (int kk = 0; kk < 4; kk++) {
            #pragma unroll
            for (int np = 0; np < 2; np++) {
                uint32_t kb[4];
                ldmx4(kb, kb_base + ((np * 16 + k_row) * 72 + kk * 16 + k_ch) * 2);
                mma16(s[2 * np],     qf[kk], kb);
                mma16(s[2 * np + 1], qf[kk], kb + 2);
            }
        }
        // ---- S_B: keys 32:63 (np=2,3) -> s[4..7]
        #pragma unroll
        for (int kk = 0; kk < 4; kk++) {
            #pragma unroll
            for (int np = 2; np < 4; np++) {
                uint32_t kb[4];
                ldmx4(kb, kb_base + ((np * 16 + k_row) * 72 + kk * 16 + k_ch) * 2);
                mma16(s[2 * np],     qf[kk], kb);
                mma16(s[2 * np + 1], qf[kk], kb + 2);
            }
        }

        // ---- sigmoid_A (fma/MUFU; overlaps S_B tensor drain)
        uint32_t paA[2][4];
        #pragma unroll
        for (int nb = 0; nb < 4; nb++) {
            float p[4];
            #pragma unroll
            for (int e = 0; e < 4; e++) {
                float y = ex2f(s[nb][e] * C1 - 11.0f);
                p[e] = y * (1.0f - y) * (1.0f + y * y);
            }
            int kkv = nb >> 1, hf = (nb & 1) << 1;
            paA[kkv][hf]     = h2(p[0], p[1]);
            paA[kkv][hf + 1] = h2(p[2], p[3]);
        }

        // ---- PV_A: keys 0:31 (kkv=0,1)
        #pragma unroll
        for (int kkv = 0; kkv < 2; kkv++) {
            #pragma unroll
            for (int j = 0; j < 4; j++) {
                uint32_t vb[4];
                ldmx4t(vb, vb_base + ((kkv * 16 + lrow) * 72 + j * 16 + lhi) * 2);
                mma16(o[2 * j],     paA[kkv], vb);
                mma16(o[2 * j + 1], paA[kkv], vb + 2);
            }
        }

        // ---- sigmoid_B (overlaps PV_A tensor occupancy)
        uint32_t paB[2][4];
        #pragma unroll
        for (int nb = 4; nb < 8; nb++) {
            float p[4];
            #pragma unroll
            for (int e = 0; e < 4; e++) {
                float y = ex2f(s[nb][e] * C1 - 11.0f);
                p[e] = y * (1.0f - y) * (1.0f + y * y);
            }
            int kkv = (nb - 4) >> 1, hf = (nb & 1) << 1;
            paB[kkv][hf]     = h2(p[0], p[1]);
            paB[kkv][hf + 1] = h2(p[2], p[3]);
        }

        // ---- PV_B: keys 32:63 (kkv=2,3)
        #pragma unroll
        for (int kkv = 2; kkv < 4; kkv++) {
            #pragma unroll
            for (int j = 0; j < 4; j++) {
                uint32_t vb[4];
                ldmx4t(vb, vb_base + ((kkv * 16 + lrow) * 72 + j * 16 + lhi) * 2);
                mma16(o[2 * j],     paB[kkv - 2], vb);
                mma16(o[2 * j + 1], paB[kkv - 2], vb + 2);
            }
        }
    }

    // ---- write O tile (fp16, 16q x 64d per warp)
    uint32_t* Aw = (uint32_t*)A +
        ((size_t)(b * SEQ + q0 + wid * 16) * DMODEL + h * DEPTH) / 2;
    #pragma unroll
    for (int nb = 0; nb < 8; nb++) {
        Aw[(size_t)g * 256 + nb * 4 + t]       = h2(o[nb][0], o[nb][1]);
        Aw[(size_t)(g + 8) * 256 + nb * 4 + t] = h2(o[nb][2], o[nb][3]);
    }
}

// ---------------------------------------------------------------------------
extern "C" void kernel_launch(void* const* d_in, const int* in_sizes, int n_in,
                              void* d_out, int out_size) {
    const float* x  = (const float*)d_in[0];
    const float* Wq = (const float*)d_in[1];
    const float* Wk = (const float*)d_in[2];
    const float* Wv = (const float*)d_in[3];
    const float* Wo = (const float*)d_in[4];
    float* out = (float*)d_out;

    __half *xh, *Wh, *Qh, *Kh, *Vh, *Ah;
    cudaGetSymbolAddress((void**)&xh, g_xh);
    cudaGetSymbolAddress((void**)&Wh, g_Wh);
    cudaGetSymbolAddress((void**)&Qh, g_Qh);
    cudaGetSymbolAddress((void**)&Kh, g_Kh);
    cudaGetSymbolAddress((void**)&Vh, g_Vh);
    cudaGetSymbolAddress((void**)&Ah, g_Ah);

    const int GSM = 110592, ASM = 55296;
    cudaFuncSetAttribute(gemm_h<1>, cudaFuncAttributeMaxDynamicSharedMemorySize, GSM);
    cudaFuncSetAttribute(gemm_h<0>, cudaFuncAttributeMaxDynamicSharedMemorySize, GSM);
    cudaFuncSetAttribute(attn_h,    cudaFuncAttributeMaxDynamicSharedMemorySize, ASM);

    const int n_total = (MROWS * DMODEL + 4 * DMODEL * DMODEL) / 4;
    cvt_all<<<(n_total + 255) / 256, 256>>>(
        (const float4*)x, (const float4*)Wq, (const float4*)Wk,
        (const float4*)Wv, (const float4*)Wo, (uint2*)xh, (uint2*)Wh);

    dim3 gq(12, MROWS / 128);            // fused QKV: 768 CTAs
    dim3 go(4, MROWS / 128);             // Wo: 256 CTAs
    dim3 ga(SEQ / 64, HEADS, BATCH);     // 1024 CTAs, 4/SM

    gemm_h<1><<<gq, 256, GSM>>>(xh, Wh, Qh, Kh, Vh);
    attn_h<<<ga, 128, ASM>>>(Qh, Kh, Vh, Ah);
    gemm_h<0><<<go, 256, GSM>>>(Ah, Wh + 3 * WSZ, out, out, out);
}